// round 16
// baseline (speedup 1.0000x reference)
#include <cuda_runtime.h>
#include <cuda_bf16.h>
#include <cstdint>

#define NN 100000
#define EE 600000
#define PP 100000
#define D  128

__device__ float g_hA[(size_t)NN * D];
__device__ float g_hB[(size_t)NN * D];
__device__ float g_agg[(size_t)NN * D];     // invariant: zero at kernel_launch entry
__device__ float g_cnt[NN];                 // same invariant
__device__ unsigned short g_bt_hi[3 * 128 * 256];   // per-layer BT[n][k]
__device__ unsigned short g_bt_lo[3 * 128 * 256];
__device__ unsigned short g_pt_hi[2 * 128 * 128];
__device__ unsigned short g_pt_lo[2 * 128 * 128];

// ---------------------------------------------------------------------------
// PTX helpers
// ---------------------------------------------------------------------------
__device__ __forceinline__ uint32_t smem_u32(const void* p) {
    uint32_t a;
    asm("{ .reg .u64 t; cvta.to.shared.u64 t, %1; cvt.u32.u64 %0, t; }"
        : "=r"(a) : "l"(p));
    return a;
}
__device__ __forceinline__ void ldsm_x4(uint32_t& r0, uint32_t& r1,
                                        uint32_t& r2, uint32_t& r3, uint32_t addr) {
    asm volatile("ldmatrix.sync.aligned.m8n8.x4.shared.b16 {%0,%1,%2,%3}, [%4];"
                 : "=r"(r0), "=r"(r1), "=r"(r2), "=r"(r3) : "r"(addr));
}
__device__ __forceinline__ void ldsm_x2(uint32_t& r0, uint32_t& r1, uint32_t addr) {
    asm volatile("ldmatrix.sync.aligned.m8n8.x2.shared.b16 {%0,%1}, [%2];"
                 : "=r"(r0), "=r"(r1) : "r"(addr));
}
__device__ __forceinline__ void mma16816(float* d, const uint32_t* a, const uint32_t* b) {
    asm volatile(
        "mma.sync.aligned.m16n8k16.row.col.f32.bf16.bf16.f32 "
        "{%0,%1,%2,%3}, {%4,%5,%6,%7}, {%8,%9}, {%0,%1,%2,%3};"
        : "+f"(d[0]), "+f"(d[1]), "+f"(d[2]), "+f"(d[3])
        : "r"(a[0]), "r"(a[1]), "r"(a[2]), "r"(a[3]), "r"(b[0]), "r"(b[1]));
}
__device__ __forceinline__ void cp16(uint32_t dst, const void* src, uint32_t sz) {
    asm volatile("cp.async.cg.shared.global [%0], [%1], 16, %2;"
                 :: "r"(dst), "l"(src), "r"(sz) : "memory");
}
#define CP_COMMIT() asm volatile("cp.async.commit_group;" ::: "memory")
#define CP_WAIT0()  asm volatile("cp.async.wait_group 0;" ::: "memory")

__device__ __forceinline__ void split4(const float4& v, uint2& hi, uint2& lo) {
    __nv_bfloat162 h0 = __floats2bfloat162_rn(v.x, v.y);
    __nv_bfloat162 h1 = __floats2bfloat162_rn(v.z, v.w);
    float2 f0 = __bfloat1622float2(h0);
    float2 f1 = __bfloat1622float2(h1);
    __nv_bfloat162 l0 = __floats2bfloat162_rn(v.x - f0.x, v.y - f0.y);
    __nv_bfloat162 l1 = __floats2bfloat162_rn(v.z - f1.x, v.w - f1.y);
    hi = make_uint2(*(uint32_t*)&h0, *(uint32_t*)&h1);
    lo = make_uint2(*(uint32_t*)&l0, *(uint32_t*)&l1);
}
__device__ __forceinline__ void split1(float v, unsigned short& hi, unsigned short& lo) {
    __nv_bfloat16 h = __float2bfloat16_rn(v);
    float r = v - __bfloat162float(h);
    __nv_bfloat16 l = __float2bfloat16_rn(r);
    hi = __bfloat16_as_ushort(h);
    lo = __bfloat16_as_ushort(l);
}

// ---------------------------------------------------------------------------
// Edge scatter
// ---------------------------------------------------------------------------
__global__ void __launch_bounds__(256) edge_kernel(
    const int* __restrict__ src, const int* __restrict__ dst,
    const float* __restrict__ w, const float* __restrict__ h)
{
    int t = blockIdx.x * blockDim.x + threadIdx.x;
    int e = t >> 5;
    if (e >= EE) return;
    int lane = t & 31;
    int s = __ldg(src + e);
    int d = __ldg(dst + e);
    float we = __ldg(w + e);
    float4 v = __ldg((const float4*)(h + (size_t)s * D) + lane);
    v.x *= we; v.y *= we; v.z *= we; v.w *= we;
    float* a = g_agg + (size_t)d * D + lane * 4;
    asm volatile("red.global.add.v4.f32 [%0], {%1,%2,%3,%4};"
                 :: "l"(a), "f"(v.x), "f"(v.y), "f"(v.z), "f"(v.w) : "memory");
    if (lane == 0) atomicAdd(g_cnt + d, 1.0f);
}

// ---------------------------------------------------------------------------
// Weight conversions (per-layer destinations)
// ---------------------------------------------------------------------------
__global__ void __launch_bounds__(256) convw_kernel(
    const float* __restrict__ Wself, const float* __restrict__ Wneigh,
    unsigned short* __restrict__ oh, unsigned short* __restrict__ ol)
{
    int idx = blockIdx.x * 256 + threadIdx.x;
    int n = idx >> 8, k = idx & 255;
    float v = (k < 128) ? __ldg(Wself + k * 128 + n)
                        : __ldg(Wneigh + (k - 128) * 128 + n);
    split1(v, oh[idx], ol[idx]);
}
__global__ void __launch_bounds__(256) convp_kernel(
    const float* __restrict__ pw1, const float* __restrict__ pw2)
{
    int idx = blockIdx.x * 256 + threadIdx.x;
    int s = idx >> 14;
    int r = idx & 16383;
    int n = r >> 7, k = r & 127;
    const float* W = s ? pw2 : pw1;
    float v = __ldg(W + k * 128 + n);
    split1(v, g_pt_hi[idx], g_pt_lo[idx]);
}

// ---------------------------------------------------------------------------
// Half node update (K=128), cp.async double-buffered bf16 3-pass MMA.
// isagg=0: out = A@Wself + bias (partial write)
// isagg=1: out = maybe_relu(out + (A/max(cnt,1))@Wneigh); zero agg,cnt
// Dynamic smem: AhiB 0/10240, AloB 20480/30720, BhiB 40960/51200,
//               BloB 61440/71680, raw 81920 (16KB) => 98304 B
// ---------------------------------------------------------------------------
#define SA 40
#define SMEM_NODE 98304

__global__ void __launch_bounds__(256, 2) sage_half_mma(
    const float* __restrict__ Ag,
    const unsigned short* __restrict__ bth,
    const unsigned short* __restrict__ btl,
    const float* __restrict__ bias,
    float* __restrict__ h_out, int isagg, int do_relu)
{
    extern __shared__ char dsm[];
    __shared__ float rcp_s[128];

    int t = threadIdx.x;
    int lane = t & 31;
    int wid = t >> 5;
    int row_blk = blockIdx.x * 128;
    int wm = wid & 3;
    int wn = wid >> 2;
    int kbase = isagg ? 128 : 0;

    uint32_t sb = smem_u32(dsm);
    uint32_t ahiB[2] = {sb,          sb + 10240};
    uint32_t aloB[2] = {sb + 20480,  sb + 30720};
    uint32_t bhiB[2] = {sb + 40960,  sb + 51200};
    uint32_t bloB[2] = {sb + 61440,  sb + 71680};
    uint32_t rawB    = sb + 81920;
    unsigned short* AhiP[2] = {(unsigned short*)dsm, (unsigned short*)(dsm + 10240)};
    unsigned short* AloP[2] = {(unsigned short*)(dsm + 20480), (unsigned short*)(dsm + 30720)};
    float* rawf = (float*)(dsm + 81920);

    auto issue_loads = [&](int kb, int b) {
        int koff = kb * 32;
        #pragma unroll
        for (int i = 0; i < 4; i++) {
            int idx = t + i * 256;
            int row = idx >> 3, q = idx & 7;
            int g = row_blk + row;
            int gc = (g < NN) ? g : (NN - 1);
            cp16(rawB + idx * 16, Ag + (size_t)gc * D + koff + q * 4,
                 (g < NN) ? 16u : 0u);
        }
        #pragma unroll
        for (int i = 0; i < 2; i++) {
            int idx = t + i * 256;
            int n = idx >> 2, kq = idx & 3;
            uint32_t doff = (uint32_t)(n * SA + kq * 8) * 2;
            cp16(bhiB[b] + doff, bth + n * 256 + kbase + kb * 32 + kq * 8, 16);
            cp16(bloB[b] + doff, btl + n * 256 + kbase + kb * 32 + kq * 8, 16);
        }
        CP_COMMIT();
    };
    auto convert = [&](int b) {
        #pragma unroll
        for (int i = 0; i < 4; i++) {
            int idx = t + i * 256;
            int row = idx >> 3, q = idx & 7;
            float4 v = *(float4*)(rawf + idx * 4);
            if (isagg) { float rc = rcp_s[row]; v.x *= rc; v.y *= rc; v.z *= rc; v.w *= rc; }
            uint2 hi, lo;
            split4(v, hi, lo);
            *(uint2*)&AhiP[b][row * SA + q * 4] = hi;
            *(uint2*)&AloP[b][row * SA + q * 4] = lo;
        }
    };

    issue_loads(0, 0);
    if (isagg && t < 128) {
        int g = row_blk + t;
        float c = (g < NN) ? g_cnt[g] : 1.0f;
        rcp_s[t] = 1.0f / fmaxf(c, 1.0f);
        if (g < NN) g_cnt[g] = 0.0f;
    }
    CP_WAIT0();
    if (isagg) __syncthreads();    // rcp_s ready before convert
    convert(0);
    __syncthreads();

    float acc[2][8][4];
    #pragma unroll
    for (int mt = 0; mt < 2; mt++)
        #pragma unroll
        for (int nt = 0; nt < 8; nt++)
            #pragma unroll
            for (int i = 0; i < 4; i++) acc[mt][nt][i] = 0.f;

    #pragma unroll 1
    for (int kb = 0; kb < 4; kb++) {
        int cur = kb & 1, nxt = cur ^ 1;
        if (kb < 3) issue_loads(kb + 1, nxt);

        #pragma unroll
        for (int kc = 0; kc < 2; kc++) {
            int k0 = kc * 16;
            uint32_t bh[8][2], bl[8][2];
            int brow = wn * 64 + (lane & 7);
            int bcol = k0 + ((lane & 8) ? 8 : 0);
            #pragma unroll
            for (int nt = 0; nt < 8; nt++) {
                uint32_t boff = (uint32_t)((brow + nt * 8) * SA + bcol) * 2;
                ldsm_x2(bh[nt][0], bh[nt][1], bhiB[cur] + boff);
                ldsm_x2(bl[nt][0], bl[nt][1], bloB[cur] + boff);
            }
            uint32_t a[2][4];
            int arow = wm * 32 + (lane & 15);
            int acol = k0 + ((lane & 16) ? 8 : 0);
            #pragma unroll
            for (int mt = 0; mt < 2; mt++)
                ldsm_x4(a[mt][0], a[mt][1], a[mt][2], a[mt][3],
                        ahiB[cur] + (uint32_t)((arow + mt * 16) * SA + acol) * 2);
            #pragma unroll
            for (int mt = 0; mt < 2; mt++)
                #pragma unroll
                for (int nt = 0; nt < 8; nt++)
                    mma16816(acc[mt][nt], a[mt], bh[nt]);
            #pragma unroll
            for (int mt = 0; mt < 2; mt++)
                #pragma unroll
                for (int nt = 0; nt < 8; nt++)
                    mma16816(acc[mt][nt], a[mt], bl[nt]);
            #pragma unroll
            for (int mt = 0; mt < 2; mt++)
                ldsm_x4(a[mt][0], a[mt][1], a[mt][2], a[mt][3],
                        aloB[cur] + (uint32_t)((arow + mt * 16) * SA + acol) * 2);
            #pragma unroll
            for (int mt = 0; mt < 2; mt++)
                #pragma unroll
                for (int nt = 0; nt < 8; nt++)
                    mma16816(acc[mt][nt], a[mt], bh[nt]);
        }

        if (kb < 3) {
            CP_WAIT0();
            convert(nxt);
        }
        __syncthreads();
    }

    int g8 = lane >> 2, tig = lane & 3;
    if (!isagg) {
        // self: out = acc + bias (partial, no relu)
        #pragma unroll
        for (int mt = 0; mt < 2; mt++) {
            int r = row_blk + wm * 32 + mt * 16 + g8;
            #pragma unroll
            for (int nt = 0; nt < 8; nt++) {
                int c = wn * 64 + nt * 8 + tig * 2;
                float2 bb = __ldg((const float2*)(bias + c));
                if (r < NN)
                    *(float2*)(h_out + (size_t)r * D + c) =
                        make_float2(acc[mt][nt][0] + bb.x, acc[mt][nt][1] + bb.y);
                if (r + 8 < NN)
                    *(float2*)(h_out + (size_t)(r + 8) * D + c) =
                        make_float2(acc[mt][nt][2] + bb.x, acc[mt][nt][3] + bb.y);
            }
        }
    } else {
        // neigh: out = maybe_relu(prev + acc)
        #pragma unroll
        for (int mt = 0; mt < 2; mt++) {
            int r = row_blk + wm * 32 + mt * 16 + g8;
            #pragma unroll
            for (int nt = 0; nt < 8; nt++) {
                int c = wn * 64 + nt * 8 + tig * 2;
                if (r < NN) {
                    float2 pv = *(float2*)(h_out + (size_t)r * D + c);
                    float o0 = pv.x + acc[mt][nt][0];
                    float o1 = pv.y + acc[mt][nt][1];
                    if (do_relu) { o0 = fmaxf(o0, 0.f); o1 = fmaxf(o1, 0.f); }
                    *(float2*)(h_out + (size_t)r * D + c) = make_float2(o0, o1);
                }
                if (r + 8 < NN) {
                    float2 pv = *(float2*)(h_out + (size_t)(r + 8) * D + c);
                    float o2 = pv.x + acc[mt][nt][2];
                    float o3 = pv.y + acc[mt][nt][3];
                    if (do_relu) { o2 = fmaxf(o2, 0.f); o3 = fmaxf(o3, 0.f); }
                    *(float2*)(h_out + (size_t)(r + 8) * D + c) = make_float2(o2, o3);
                }
            }
        }
        // restore zero invariant on g_agg rows owned by this block
        float4 z4 = make_float4(0.f, 0.f, 0.f, 0.f);
        #pragma unroll
        for (int i = 0; i < 16; i++) {
            int idx = t + i * 256;
            int row = idx >> 5, q = idx & 31;
            int g = row_blk + row;
            if (g < NN) *(float4*)(g_agg + (size_t)g * D + q * 4) = z4;
        }
    }
}

// ---------------------------------------------------------------------------
// Link predictor (R15, unchanged): full-K A tiles, chunked B tiles, 2 CTA/SM.
// ---------------------------------------------------------------------------
#define PB 782
#define SAP 136
#define SMEM_PRED 90112

__global__ void __launch_bounds__(256, 2) pred_mma(
    const float* __restrict__ h,
    const int* __restrict__ pos_a, const int* __restrict__ pos_b,
    const int* __restrict__ neg_a, const int* __restrict__ neg_b,
    const float* __restrict__ pb1, const float* __restrict__ pb2,
    const float* __restrict__ pw3, const float* __restrict__ pb3,
    float* __restrict__ out)
{
    extern __shared__ char dsm[];
    unsigned short* Ahi = (unsigned short*)dsm;
    unsigned short* Alo = (unsigned short*)(dsm + 34816);
    unsigned short* Bhi = (unsigned short*)(dsm + 69632);
    unsigned short* Blo = (unsigned short*)(dsm + 79872);
    __shared__ float red[128][2];

    int t = threadIdx.x;
    int lane = t & 31;
    int wid = t >> 5;
    int wm = wid & 3;
    int wn = wid >> 2;

    bool is_neg = blockIdx.x >= PB;
    int p0 = (is_neg ? (blockIdx.x - PB) : blockIdx.x) * 128;
    const int* ia = is_neg ? neg_a : pos_a;
    const int* ib = is_neg ? neg_b : pos_b;
    float* outp = out + (is_neg ? PP : 0);

    uint32_t ahi_b = smem_u32(Ahi), alo_b = smem_u32(Alo);
    uint32_t bhi_b = smem_u32(Bhi), blo_b = smem_u32(Blo);

    {
        int p = t >> 1;
        int half = t & 1;
        int gp = p0 + p;
        bool valid = gp < PP;
        int sa = valid ? __ldg(ia + gp) : 0;
        int sb = valid ? __ldg(ib + gp) : 0;
        const float4* ha = (const float4*)(h + (size_t)sa * D) + half * 16;
        const float4* hb = (const float4*)(h + (size_t)sb * D) + half * 16;
        #pragma unroll
        for (int i = 0; i < 16; i += 2) {
            float4 va = __ldg(ha + i), va2 = __ldg(ha + i + 1);
            float4 vb = __ldg(hb + i), vb2 = __ldg(hb + i + 1);
            float4 z = make_float4(va.x * vb.x, va.y * vb.y, va.z * vb.z, va.w * vb.w);
            float4 z2 = make_float4(va2.x * vb2.x, va2.y * vb2.y, va2.z * vb2.z, va2.w * vb2.w);
            uint2 hi, lo, hi2, lo2;
            split4(z, hi, lo);
            split4(z2, hi2, lo2);
            int o = p * SAP + half * 64 + i * 4;
            *(uint4*)&Ahi[o] = make_uint4(hi.x, hi.y, hi2.x, hi2.y);
            *(uint4*)&Alo[o] = make_uint4(lo.x, lo.y, lo2.x, lo2.y);
        }
    }

    float acc[2][8][4];
    int g8 = lane >> 2, tig = lane & 3;

    #pragma unroll 1
    for (int stage = 0; stage < 2; stage++) {
        const unsigned short* ph = g_pt_hi + stage * 16384;
        const unsigned short* pl = g_pt_lo + stage * 16384;

        #pragma unroll
        for (int mt = 0; mt < 2; mt++)
            #pragma unroll
            for (int nt = 0; nt < 8; nt++)
                #pragma unroll
                for (int i = 0; i < 4; i++) acc[mt][nt][i] = 0.f;

        #pragma unroll 1
        for (int kb = 0; kb < 4; kb++) {
            __syncthreads();
            #pragma unroll
            for (int i = 0; i < 2; i++) {
                int idx = t + i * 256;
                int n = idx >> 2, kq = idx & 3;
                *(uint4*)&Bhi[n * SA + kq * 8] =
                    __ldg((const uint4*)(ph + n * 128 + kb * 32 + kq * 8));
                *(uint4*)&Blo[n * SA + kq * 8] =
                    __ldg((const uint4*)(pl + n * 128 + kb * 32 + kq * 8));
            }
            __syncthreads();

            #pragma unroll
            for (int kc = 0; kc < 2; kc++) {
                int k0 = kc * 16;
                uint32_t bh[8][2], bl[8][2];
                int brow = wn * 64 + (lane & 7);
                int bcol = k0 + ((lane & 8) ? 8 : 0);
                #pragma unroll
                for (int nt = 0; nt < 8; nt++) {
                    uint32_t boff = (uint32_t)((brow + nt * 8) * SA + bcol) * 2;
                    ldsm_x2(bh[nt][0], bh[nt][1], bhi_b + boff);
                    ldsm_x2(bl[nt][0], bl[nt][1], blo_b + boff);
                }
                uint32_t a[2][4];
                int arow = wm * 32 + (lane & 15);
                int acol = kb * 32 + k0 + ((lane & 16) ? 8 : 0);
                #pragma unroll
                for (int mt = 0; mt < 2; mt++)
                    ldsm_x4(a[mt][0], a[mt][1], a[mt][2], a[mt][3],
                            ahi_b + (uint32_t)((arow + mt * 16) * SAP + acol) * 2);
                #pragma unroll
                for (int mt = 0; mt < 2; mt++)
                    #pragma unroll
                    for (int nt = 0; nt < 8; nt++)
                        mma16816(acc[mt][nt], a[mt], bh[nt]);
                #pragma unroll
                for (int mt = 0; mt < 2; mt++)
                    #pragma unroll
                    for (int nt = 0; nt < 8; nt++)
                        mma16816(acc[mt][nt], a[mt], bl[nt]);
                #pragma unroll
                for (int mt = 0; mt < 2; mt++)
                    ldsm_x4(a[mt][0], a[mt][1], a[mt][2], a[mt][3],
                            alo_b + (uint32_t)((arow + mt * 16) * SAP + acol) * 2);
                #pragma unroll
                for (int mt = 0; mt < 2; mt++)
                    #pragma unroll
                    for (int nt = 0; nt < 8; nt++)
                        mma16816(acc[mt][nt], a[mt], bh[nt]);
            }
        }
        __syncthreads();

        if (stage == 0) {
            #pragma unroll
            for (int mt = 0; mt < 2; mt++) {
                int r = wm * 32 + mt * 16 + g8;
                #pragma unroll
                for (int nt = 0; nt < 8; nt++) {
                    int c = wn * 64 + nt * 8 + tig * 2;
                    float2 bb = __ldg((const float2*)(pb1 + c));
                    float v0 = fmaxf(acc[mt][nt][0] + bb.x, 0.f);
                    float v1 = fmaxf(acc[mt][nt][1] + bb.y, 0.f);
                    float v2 = fmaxf(acc[mt][nt][2] + bb.x, 0.f);
                    float v3 = fmaxf(acc[mt][nt][3] + bb.y, 0.f);
                    unsigned short h0, l0, h1, l1, h2, l2, h3, l3;
                    split1(v0, h0, l0); split1(v1, h1, l1);
                    split1(v2, h2, l2); split1(v3, h3, l3);
                    Ahi[r * SAP + c] = h0;       Ahi[r * SAP + c + 1] = h1;
                    Alo[r * SAP + c] = l0;       Alo[r * SAP + c + 1] = l1;
                    Ahi[(r + 8) * SAP + c] = h2; Ahi[(r + 8) * SAP + c + 1] = h3;
                    Alo[(r + 8) * SAP + c] = l2; Alo[(r + 8) * SAP + c + 1] = l3;
                }
            }
        }
    }

    {
        float s0 = 0.f, s1 = 0.f, s2 = 0.f, s3 = 0.f;
        #pragma unroll
        for (int nt = 0; nt < 8; nt++) {
            int c = wn * 64 + nt * 8 + tig * 2;
            float2 bb = __ldg((const float2*)(pb2 + c));
            float w0 = __ldg(pw3 + c);
            float w1 = __ldg(pw3 + c + 1);
            s0 += fmaxf(acc[0][nt][0] + bb.x, 0.f) * w0 + fmaxf(acc[0][nt][1] + bb.y, 0.f) * w1;
            s1 += fmaxf(acc[0][nt][2] + bb.x, 0.f) * w0 + fmaxf(acc[0][nt][3] + bb.y, 0.f) * w1;
            s2 += fmaxf(acc[1][nt][0] + bb.x, 0.f) * w0 + fmaxf(acc[1][nt][1] + bb.y, 0.f) * w1;
            s3 += fmaxf(acc[1][nt][2] + bb.x, 0.f) * w0 + fmaxf(acc[1][nt][3] + bb.y, 0.f) * w1;
        }
        #pragma unroll
        for (int dd = 1; dd < 4; dd <<= 1) {
            s0 += __shfl_xor_sync(0xffffffffu, s0, dd);
            s1 += __shfl_xor_sync(0xffffffffu, s1, dd);
            s2 += __shfl_xor_sync(0xffffffffu, s2, dd);
            s3 += __shfl_xor_sync(0xffffffffu, s3, dd);
        }
        if (tig == 0) {
            int r = wm * 32 + g8;
            red[r][wn]      = s0;
            red[r + 8][wn]  = s1;
            red[r + 16][wn] = s2;
            red[r + 24][wn] = s3;
        }
    }
    __syncthreads();
    if (t < 128 && p0 + t < PP)
        outp[p0 + t] = red[t][0] + red[t][1] + __ldg(pb3);
}

// ---------------------------------------------------------------------------
extern "C" void kernel_launch(void* const* d_in, const int* in_sizes, int n_in,
                              void* d_out, int out_size)
{
    const float* x     = (const float*)d_in[0];
    const int* src[3]  = {(const int*)d_in[1], (const int*)d_in[4], (const int*)d_in[7]};
    const int* dst[3]  = {(const int*)d_in[2], (const int*)d_in[5], (const int*)d_in[8]};
    const float* w[3]  = {(const float*)d_in[3], (const float*)d_in[6], (const float*)d_in[9]};
    const int* pos_src = (const int*)d_in[10];
    const int* pos_dst = (const int*)d_in[11];
    const int* neg_src = (const int*)d_in[12];
    const int* neg_dst = (const int*)d_in[13];
    const float* Wself[3]  = {(const float*)d_in[14], (const float*)d_in[17], (const float*)d_in[20]};
    const float* Wneigh[3] = {(const float*)d_in[15], (const float*)d_in[18], (const float*)d_in[21]};
    const float* bvec[3]   = {(const float*)d_in[16], (const float*)d_in[19], (const float*)d_in[22]};
    const float* pw1 = (const float*)d_in[23];
    const float* pb1 = (const float*)d_in[24];
    const float* pw2 = (const float*)d_in[25];
    const float* pb2 = (const float*)d_in[26];
    const float* pw3 = (const float*)d_in[27];
    const float* pb3 = (const float*)d_in[28];

    float* out = (float*)d_out;
    float* h_final = out + 2 * PP;

    void *hA_p, *hB_p, *agg_p, *bth_p, *btl_p;
    cudaGetSymbolAddress(&hA_p, g_hA);
    cudaGetSymbolAddress(&hB_p, g_hB);
    cudaGetSymbolAddress(&agg_p, g_agg);
    cudaGetSymbolAddress(&bth_p, g_bt_hi);
    cudaGetSymbolAddress(&btl_p, g_bt_lo);
    float* hA = (float*)hA_p;
    float* hB = (float*)hB_p;
    const float* agg = (const float*)agg_p;
    unsigned short* bth = (unsigned short*)bth_p;
    unsigned short* btl = (unsigned short*)btl_p;

    static cudaStream_t s1 = nullptr;
    static cudaEvent_t evF[3], evJ[3];
    static bool init_done = false;
    if (!init_done) {
        cudaFuncSetAttribute(sage_half_mma, cudaFuncAttributeMaxDynamicSharedMemorySize, SMEM_NODE);
        cudaFuncSetAttribute(pred_mma, cudaFuncAttributeMaxDynamicSharedMemorySize, SMEM_PRED);
        cudaStreamCreateWithFlags(&s1, cudaStreamNonBlocking);
        for (int i = 0; i < 3; i++) {
            cudaEventCreateWithFlags(&evF[i], cudaEventDisableTiming);
            cudaEventCreateWithFlags(&evJ[i], cudaEventDisableTiming);
        }
        init_done = true;
    }

    const int edge_blocks = (EE * 32 + 255) / 256;
    const int node_blocks = (NN + 127) / 128;

    const float* layer_in[3]  = {x, hA, hB};
    float*       layer_out[3] = {hA, hB, h_final};

    convp_kernel<<<128, 256>>>(pw1, pw2);
    for (int l = 0; l < 3; l++)
        convw_kernel<<<128, 256>>>(Wself[l], Wneigh[l],
                                   bth + l * 32768, btl + l * 32768);

    for (int l = 0; l < 3; l++) {
        // fork: self-GEMM on s1, edge scatter on default stream
        cudaEventRecord(evF[l], 0);
        cudaStreamWaitEvent(s1, evF[l], 0);
        sage_half_mma<<<node_blocks, 256, SMEM_NODE, s1>>>(
            layer_in[l], bth + l * 32768, btl + l * 32768,
            bvec[l], layer_out[l], 0, 0);
        cudaEventRecord(evJ[l], s1);

        edge_kernel<<<edge_blocks, 256>>>(src[l], dst[l], w[l], layer_in[l]);

        // join, then neigh-GEMM (accumulate + relu)
        cudaStreamWaitEvent(0, evJ[l], 0);
        sage_half_mma<<<node_blocks, 256, SMEM_NODE>>>(
            agg, bth + l * 32768, btl + l * 32768,
            nullptr, layer_out[l], 1, l < 2 ? 1 : 0);
    }

    pred_mma<<<2 * PB, 256, SMEM_PRED>>>(h_final, pos_src, pos_dst, neg_src, neg_dst,
                                         pb1, pb2, pw3, pb3, out);
}

// round 17
// speedup vs baseline: 1.2772x; 1.2772x over previous
#include <cuda_runtime.h>
#include <cuda_bf16.h>
#include <cstdint>

#define NN 100000
#define EE 600000
#define PP 100000
#define D  128

#define SCAN_BLKS 391          // ceil(100096/256)
#define EDGE_BLKS 2344         // ceil(600000/256)

__device__ float g_hA[(size_t)NN * D];
__device__ float g_hB[(size_t)NN * D];
__device__ float g_agg[(size_t)NN * D];
__device__ int   g_hist[NN];            // invariant: zero at entry (restored each layer)
__device__ int   g_off[NN + 1];
__device__ int   g_pos[NN];
__device__ int   g_bsum[SCAN_BLKS];
__device__ int2  g_edata[EE];           // CSR: (src, w-bits)
__device__ unsigned short g_bt_hi[3 * 128 * 256];
__device__ unsigned short g_bt_lo[3 * 128 * 256];
__device__ unsigned short g_pt_hi[2 * 128 * 128];
__device__ unsigned short g_pt_lo[2 * 128 * 128];

// ---------------------------------------------------------------------------
// PTX helpers
// ---------------------------------------------------------------------------
__device__ __forceinline__ uint32_t smem_u32(const void* p) {
    uint32_t a;
    asm("{ .reg .u64 t; cvta.to.shared.u64 t, %1; cvt.u32.u64 %0, t; }"
        : "=r"(a) : "l"(p));
    return a;
}
__device__ __forceinline__ void ldsm_x4(uint32_t& r0, uint32_t& r1,
                                        uint32_t& r2, uint32_t& r3, uint32_t addr) {
    asm volatile("ldmatrix.sync.aligned.m8n8.x4.shared.b16 {%0,%1,%2,%3}, [%4];"
                 : "=r"(r0), "=r"(r1), "=r"(r2), "=r"(r3) : "r"(addr));
}
__device__ __forceinline__ void mma16816(float* d, const uint32_t* a, const uint32_t* b) {
    asm volatile(
        "mma.sync.aligned.m16n8k16.row.col.f32.bf16.bf16.f32 "
        "{%0,%1,%2,%3}, {%4,%5,%6,%7}, {%8,%9}, {%0,%1,%2,%3};"
        : "+f"(d[0]), "+f"(d[1]), "+f"(d[2]), "+f"(d[3])
        : "r"(a[0]), "r"(a[1]), "r"(a[2]), "r"(a[3]), "r"(b[0]), "r"(b[1]));
}
__device__ __forceinline__ void cp16(uint32_t dst, const void* src, uint32_t sz) {
    asm volatile("cp.async.cg.shared.global [%0], [%1], 16, %2;"
                 :: "r"(dst), "l"(src), "r"(sz) : "memory");
}
#define CP_COMMIT() asm volatile("cp.async.commit_group;" ::: "memory")
#define CP_WAIT0()  asm volatile("cp.async.wait_group 0;" ::: "memory")

__device__ __forceinline__ void split4(const float4& v, uint2& hi, uint2& lo) {
    __nv_bfloat162 h0 = __floats2bfloat162_rn(v.x, v.y);
    __nv_bfloat162 h1 = __floats2bfloat162_rn(v.z, v.w);
    float2 f0 = __bfloat1622float2(h0);
    float2 f1 = __bfloat1622float2(h1);
    __nv_bfloat162 l0 = __floats2bfloat162_rn(v.x - f0.x, v.y - f0.y);
    __nv_bfloat162 l1 = __floats2bfloat162_rn(v.z - f1.x, v.w - f1.y);
    hi = make_uint2(*(uint32_t*)&h0, *(uint32_t*)&h1);
    lo = make_uint2(*(uint32_t*)&l0, *(uint32_t*)&l1);
}
__device__ __forceinline__ void split1(float v, unsigned short& hi, unsigned short& lo) {
    __nv_bfloat16 h = __float2bfloat16_rn(v);
    float r = v - __bfloat162float(h);
    __nv_bfloat16 l = __float2bfloat16_rn(r);
    hi = __bfloat16_as_ushort(h);
    lo = __bfloat16_as_ushort(l);
}

// ---------------------------------------------------------------------------
// CSR build: hist -> scan (3 kernels) -> scatter
// ---------------------------------------------------------------------------
__global__ void __launch_bounds__(256) hist_kernel(const int* __restrict__ dst) {
    int e = blockIdx.x * 256 + threadIdx.x;
    if (e < EE) atomicAdd(&g_hist[__ldg(dst + e)], 1);
}

__global__ void __launch_bounds__(256) scan1_kernel() {
    __shared__ int sd[256];
    int t = threadIdx.x;
    int i = blockIdx.x * 256 + t;
    sd[t] = (i < NN) ? g_hist[i] : 0;
    __syncthreads();
    #pragma unroll
    for (int s = 128; s > 0; s >>= 1) {
        if (t < s) sd[t] += sd[t + s];
        __syncthreads();
    }
    if (t == 0) g_bsum[blockIdx.x] = sd[0];
}

__global__ void __launch_bounds__(512) scan2_kernel() {
    __shared__ int sd[512];
    int t = threadIdx.x;
    int v = (t < SCAN_BLKS) ? g_bsum[t] : 0;
    sd[t] = v;
    __syncthreads();
    #pragma unroll
    for (int d = 1; d < 512; d <<= 1) {
        int x = sd[t];
        if (t >= d) x += sd[t - d];
        __syncthreads();
        sd[t] = x;
        __syncthreads();
    }
    if (t < SCAN_BLKS) g_bsum[t] = sd[t] - v;   // exclusive
}

__global__ void __launch_bounds__(256) scan3_kernel() {
    __shared__ int sd[256];
    int t = threadIdx.x;
    int i = blockIdx.x * 256 + t;
    int v = (i < NN) ? g_hist[i] : 0;
    sd[t] = v;
    __syncthreads();
    #pragma unroll
    for (int d = 1; d < 256; d <<= 1) {
        int x = sd[t];
        if (t >= d) x += sd[t - d];
        __syncthreads();
        sd[t] = x;
        __syncthreads();
    }
    int excl = sd[t] - v + g_bsum[blockIdx.x];
    if (i < NN) {
        g_off[i] = excl;
        g_pos[i] = excl;
        g_hist[i] = 0;                 // restore zero invariant
        if (i == NN - 1) g_off[NN] = EE;
    }
}

__global__ void __launch_bounds__(256) scatter_kernel(
    const int* __restrict__ src, const int* __restrict__ dst,
    const float* __restrict__ w)
{
    int e = blockIdx.x * 256 + threadIdx.x;
    if (e >= EE) return;
    int d = __ldg(dst + e);
    int slot = atomicAdd(&g_pos[d], 1);
    g_edata[slot] = make_int2(__ldg(src + e), __float_as_int(__ldg(w + e)));
}

// ---------------------------------------------------------------------------
// Aggregation: one warp per node, registers only, mean applied here.
// ---------------------------------------------------------------------------
__global__ void __launch_bounds__(256) aggregate_kernel(const float* __restrict__ h) {
    int wl = threadIdx.x >> 5;
    int lane = threadIdx.x & 31;
    int n = blockIdx.x * 8 + wl;
    if (n >= NN) return;
    int beg = __ldg(g_off + n), end = __ldg(g_off + n + 1);
    float4 acc = make_float4(0.f, 0.f, 0.f, 0.f);
    int e = beg;
    for (; e + 1 < end; e += 2) {
        int2 d0 = __ldg(g_edata + e);
        int2 d1 = __ldg(g_edata + e + 1);
        float w0 = __int_as_float(d0.y), w1 = __int_as_float(d1.y);
        float4 v0 = __ldg((const float4*)(h + (size_t)d0.x * D) + lane);
        float4 v1 = __ldg((const float4*)(h + (size_t)d1.x * D) + lane);
        acc.x += w0 * v0.x + w1 * v1.x;
        acc.y += w0 * v0.y + w1 * v1.y;
        acc.z += w0 * v0.z + w1 * v1.z;
        acc.w += w0 * v0.w + w1 * v1.w;
    }
    if (e < end) {
        int2 d0 = __ldg(g_edata + e);
        float w0 = __int_as_float(d0.y);
        float4 v0 = __ldg((const float4*)(h + (size_t)d0.x * D) + lane);
        acc.x += w0 * v0.x; acc.y += w0 * v0.y;
        acc.z += w0 * v0.z; acc.w += w0 * v0.w;
    }
    float sc = 1.0f / (float)max(end - beg, 1);
    acc.x *= sc; acc.y *= sc; acc.z *= sc; acc.w *= sc;
    *(float4*)(g_agg + (size_t)n * D + lane * 4) = acc;
}

// ---------------------------------------------------------------------------
// Weight conversions
// ---------------------------------------------------------------------------
__global__ void __launch_bounds__(256) convw_kernel(
    const float* __restrict__ Wself, const float* __restrict__ Wneigh,
    unsigned short* __restrict__ oh, unsigned short* __restrict__ ol)
{
    int idx = blockIdx.x * 256 + threadIdx.x;
    int n = idx >> 8, k = idx & 255;
    float v = (k < 128) ? __ldg(Wself + k * 128 + n)
                        : __ldg(Wneigh + (k - 128) * 128 + n);
    split1(v, oh[idx], ol[idx]);
}
__global__ void __launch_bounds__(256) convp_kernel(
    const float* __restrict__ pw1, const float* __restrict__ pw2)
{
    int idx = blockIdx.x * 256 + threadIdx.x;
    int s = idx >> 14;
    int r = idx & 16383;
    int n = r >> 7, k = r & 127;
    const float* W = s ? pw2 : pw1;
    float v = __ldg(W + k * 128 + n);
    split1(v, g_pt_hi[idx], g_pt_lo[idx]);
}

// ---------------------------------------------------------------------------
// Node GEMM: out = [h | agg] @ [Wself;Wneigh] + b (optional ReLU).
// cp.async double-buffered bf16 3-pass MMA. agg is pre-divided by cnt.
// ---------------------------------------------------------------------------
#define SA 40
#define SMEM_NODE 98304

__global__ void __launch_bounds__(256, 2) sage_node_mma(
    const float* __restrict__ h_in,
    const unsigned short* __restrict__ bth,
    const unsigned short* __restrict__ btl,
    const float* __restrict__ bias,
    float* __restrict__ h_out, int do_relu)
{
    extern __shared__ char dsm[];
    int t = threadIdx.x;
    int lane = t & 31;
    int wid = t >> 5;
    int row_blk = blockIdx.x * 128;
    int wm = wid & 3;
    int wn = wid >> 2;

    uint32_t sb = smem_u32(dsm);
    uint32_t ahiB[2] = {sb,          sb + 10240};
    uint32_t aloB[2] = {sb + 20480,  sb + 30720};
    uint32_t bhiB[2] = {sb + 40960,  sb + 51200};
    uint32_t bloB[2] = {sb + 61440,  sb + 71680};
    uint32_t rawB    = sb + 81920;
    unsigned short* AhiP[2] = {(unsigned short*)dsm, (unsigned short*)(dsm + 10240)};
    unsigned short* AloP[2] = {(unsigned short*)(dsm + 20480), (unsigned short*)(dsm + 30720)};
    float* rawf = (float*)(dsm + 81920);

    auto issue_loads = [&](int kb, int b) {
        const float* Ab = (kb < 4) ? h_in : g_agg;
        int koff = (kb & 3) * 32;
        #pragma unroll
        for (int i = 0; i < 4; i++) {
            int idx = t + i * 256;
            int row = idx >> 3, q = idx & 7;
            int g = row_blk + row;
            int gc = (g < NN) ? g : (NN - 1);
            cp16(rawB + idx * 16, Ab + (size_t)gc * D + koff + q * 4,
                 (g < NN) ? 16u : 0u);
        }
        #pragma unroll
        for (int i = 0; i < 2; i++) {
            int idx = t + i * 256;
            int n = idx >> 2, kq = idx & 3;
            uint32_t doff = (uint32_t)(n * SA + kq * 8) * 2;
            cp16(bhiB[b] + doff, bth + n * 256 + kb * 32 + kq * 8, 16);
            cp16(bloB[b] + doff, btl + n * 256 + kb * 32 + kq * 8, 16);
        }
        CP_COMMIT();
    };
    auto convert = [&](int b) {
        #pragma unroll
        for (int i = 0; i < 4; i++) {
            int idx = t + i * 256;
            int row = idx >> 3, q = idx & 7;
            float4 v = *(float4*)(rawf + idx * 4);
            uint2 hi, lo;
            split4(v, hi, lo);
            *(uint2*)&AhiP[b][row * SA + q * 4] = hi;
            *(uint2*)&AloP[b][row * SA + q * 4] = lo;
        }
    };

    issue_loads(0, 0);
    CP_WAIT0();
    convert(0);
    __syncthreads();

    float acc[2][8][4];
    #pragma unroll
    for (int mt = 0; mt < 2; mt++)
        #pragma unroll
        for (int nt = 0; nt < 8; nt++)
            #pragma unroll
            for (int i = 0; i < 4; i++) acc[mt][nt][i] = 0.f;

    #pragma unroll 1
    for (int kb = 0; kb < 8; kb++) {
        int cur = kb & 1, nxt = cur ^ 1;
        if (kb < 7) issue_loads(kb + 1, nxt);

        #pragma unroll
        for (int kc = 0; kc < 2; kc++) {
            int k0 = kc * 16;
            uint32_t bh[8][2], bl[8][2];
            int brow = wn * 64 + (lane & 7) + ((lane & 16) ? 8 : 0);
            int bcol = k0 + ((lane & 8) ? 8 : 0);
            #pragma unroll
            for (int nt = 0; nt < 8; nt += 2) {
                uint32_t boff = (uint32_t)((brow + nt * 8) * SA + bcol) * 2;
                ldsm_x4(bh[nt][0], bh[nt][1], bh[nt + 1][0], bh[nt + 1][1], bhiB[cur] + boff);
                ldsm_x4(bl[nt][0], bl[nt][1], bl[nt + 1][0], bl[nt + 1][1], bloB[cur] + boff);
            }
            uint32_t a[2][4];
            int arow = wm * 32 + (lane & 15);
            int acol = k0 + ((lane & 16) ? 8 : 0);
            #pragma unroll
            for (int mt = 0; mt < 2; mt++)
                ldsm_x4(a[mt][0], a[mt][1], a[mt][2], a[mt][3],
                        ahiB[cur] + (uint32_t)((arow + mt * 16) * SA + acol) * 2);
            #pragma unroll
            for (int mt = 0; mt < 2; mt++)
                #pragma unroll
                for (int nt = 0; nt < 8; nt++)
                    mma16816(acc[mt][nt], a[mt], bh[nt]);
            #pragma unroll
            for (int mt = 0; mt < 2; mt++)
                #pragma unroll
                for (int nt = 0; nt < 8; nt++)
                    mma16816(acc[mt][nt], a[mt], bl[nt]);
            #pragma unroll
            for (int mt = 0; mt < 2; mt++)
                ldsm_x4(a[mt][0], a[mt][1], a[mt][2], a[mt][3],
                        aloB[cur] + (uint32_t)((arow + mt * 16) * SA + acol) * 2);
            #pragma unroll
            for (int mt = 0; mt < 2; mt++)
                #pragma unroll
                for (int nt = 0; nt < 8; nt++)
                    mma16816(acc[mt][nt], a[mt], bh[nt]);
        }

        if (kb < 7) {
            CP_WAIT0();
            convert(nxt);
        }
        __syncthreads();
    }

    int g8 = lane >> 2, tig = lane & 3;
    #pragma unroll
    for (int mt = 0; mt < 2; mt++) {
        int r = row_blk + wm * 32 + mt * 16 + g8;
        #pragma unroll
        for (int nt = 0; nt < 8; nt++) {
            int c = wn * 64 + nt * 8 + tig * 2;
            float2 bb = __ldg((const float2*)(bias + c));
            float o0 = acc[mt][nt][0] + bb.x;
            float o1 = acc[mt][nt][1] + bb.y;
            float o2 = acc[mt][nt][2] + bb.x;
            float o3 = acc[mt][nt][3] + bb.y;
            if (do_relu) {
                o0 = fmaxf(o0, 0.f); o1 = fmaxf(o1, 0.f);
                o2 = fmaxf(o2, 0.f); o3 = fmaxf(o3, 0.f);
            }
            if (r < NN)     *(float2*)(h_out + (size_t)r * D + c)       = make_float2(o0, o1);
            if (r + 8 < NN) *(float2*)(h_out + (size_t)(r + 8) * D + c) = make_float2(o2, o3);
        }
    }
}

// ---------------------------------------------------------------------------
// Link predictor (R15 structure, B via ldsm_x4)
// ---------------------------------------------------------------------------
#define PB 782
#define SAP 136
#define SMEM_PRED 90112

__global__ void __launch_bounds__(256, 2) pred_mma(
    const float* __restrict__ h,
    const int* __restrict__ pos_a, const int* __restrict__ pos_b,
    const int* __restrict__ neg_a, const int* __restrict__ neg_b,
    const float* __restrict__ pb1, const float* __restrict__ pb2,
    const float* __restrict__ pw3, const float* __restrict__ pb3,
    float* __restrict__ out)
{
    extern __shared__ char dsm[];
    unsigned short* Ahi = (unsigned short*)dsm;
    unsigned short* Alo = (unsigned short*)(dsm + 34816);
    unsigned short* Bhi = (unsigned short*)(dsm + 69632);
    unsigned short* Blo = (unsigned short*)(dsm + 79872);
    __shared__ float red[128][2];

    int t = threadIdx.x;
    int lane = t & 31;
    int wid = t >> 5;
    int wm = wid & 3;
    int wn = wid >> 2;

    bool is_neg = blockIdx.x >= PB;
    int p0 = (is_neg ? (blockIdx.x - PB) : blockIdx.x) * 128;
    const int* ia = is_neg ? neg_a : pos_a;
    const int* ib = is_neg ? neg_b : pos_b;
    float* outp = out + (is_neg ? PP : 0);

    uint32_t ahi_b = smem_u32(Ahi), alo_b = smem_u32(Alo);
    uint32_t bhi_b = smem_u32(Bhi), blo_b = smem_u32(Blo);

    {
        int p = t >> 1;
        int half = t & 1;
        int gp = p0 + p;
        bool valid = gp < PP;
        int sa = valid ? __ldg(ia + gp) : 0;
        int sb = valid ? __ldg(ib + gp) : 0;
        const float4* ha = (const float4*)(h + (size_t)sa * D) + half * 16;
        const float4* hb = (const float4*)(h + (size_t)sb * D) + half * 16;
        #pragma unroll
        for (int i = 0; i < 16; i += 2) {
            float4 va = __ldg(ha + i), va2 = __ldg(ha + i + 1);
            float4 vb = __ldg(hb + i), vb2 = __ldg(hb + i + 1);
            float4 z = make_float4(va.x * vb.x, va.y * vb.y, va.z * vb.z, va.w * vb.w);
            float4 z2 = make_float4(va2.x * vb2.x, va2.y * vb2.y, va2.z * vb2.z, va2.w * vb2.w);
            uint2 hi, lo, hi2, lo2;
            split4(z, hi, lo);
            split4(z2, hi2, lo2);
            int o = p * SAP + half * 64 + i * 4;
            *(uint4*)&Ahi[o] = make_uint4(hi.x, hi.y, hi2.x, hi2.y);
            *(uint4*)&Alo[o] = make_uint4(lo.x, lo.y, lo2.x, lo2.y);
        }
    }

    float acc[2][8][4];
    int g8 = lane >> 2, tig = lane & 3;

    #pragma unroll 1
    for (int stage = 0; stage < 2; stage++) {
        const unsigned short* ph = g_pt_hi + stage * 16384;
        const unsigned short* pl = g_pt_lo + stage * 16384;

        #pragma unroll
        for (int mt = 0; mt < 2; mt++)
            #pragma unroll
            for (int nt = 0; nt < 8; nt++)
                #pragma unroll
                for (int i = 0; i < 4; i++) acc[mt][nt][i] = 0.f;

        #pragma unroll 1
        for (int kb = 0; kb < 4; kb++) {
            __syncthreads();
            #pragma unroll
            for (int i = 0; i < 2; i++) {
                int idx = t + i * 256;
                int n = idx >> 2, kq = idx & 3;
                *(uint4*)&Bhi[n * SA + kq * 8] =
                    __ldg((const uint4*)(ph + n * 128 + kb * 32 + kq * 8));
                *(uint4*)&Blo[n * SA + kq * 8] =
                    __ldg((const uint4*)(pl + n * 128 + kb * 32 + kq * 8));
            }
            __syncthreads();

            #pragma unroll
            for (int kc = 0; kc < 2; kc++) {
                int k0 = kc * 16;
                uint32_t bh[8][2], bl[8][2];
                int brow = wn * 64 + (lane & 7) + ((lane & 16) ? 8 : 0);
                int bcol = k0 + ((lane & 8) ? 8 : 0);
                #pragma unroll
                for (int nt = 0; nt < 8; nt += 2) {
                    uint32_t boff = (uint32_t)((brow + nt * 8) * SA + bcol) * 2;
                    ldsm_x4(bh[nt][0], bh[nt][1], bh[nt + 1][0], bh[nt + 1][1], bhi_b + boff);
                    ldsm_x4(bl[nt][0], bl[nt][1], bl[nt + 1][0], bl[nt + 1][1], blo_b + boff);
                }
                uint32_t a[2][4];
                int arow = wm * 32 + (lane & 15);
                int acol = kb * 32 + k0 + ((lane & 16) ? 8 : 0);
                #pragma unroll
                for (int mt = 0; mt < 2; mt++)
                    ldsm_x4(a[mt][0], a[mt][1], a[mt][2], a[mt][3],
                            ahi_b + (uint32_t)((arow + mt * 16) * SAP + acol) * 2);
                #pragma unroll
                for (int mt = 0; mt < 2; mt++)
                    #pragma unroll
                    for (int nt = 0; nt < 8; nt++)
                        mma16816(acc[mt][nt], a[mt], bh[nt]);
                #pragma unroll
                for (int mt = 0; mt < 2; mt++)
                    #pragma unroll
                    for (int nt = 0; nt < 8; nt++)
                        mma16816(acc[mt][nt], a[mt], bl[nt]);
                #pragma unroll
                for (int mt = 0; mt < 2; mt++)
                    ldsm_x4(a[mt][0], a[mt][1], a[mt][2], a[mt][3],
                            alo_b + (uint32_t)((arow + mt * 16) * SAP + acol) * 2);
                #pragma unroll
                for (int mt = 0; mt < 2; mt++)
                    #pragma unroll
                    for (int nt = 0; nt < 8; nt++)
                        mma16816(acc[mt][nt], a[mt], bh[nt]);
            }
        }
        __syncthreads();

        if (stage == 0) {
            #pragma unroll
            for (int mt = 0; mt < 2; mt++) {
                int r = wm * 32 + mt * 16 + g8;
                #pragma unroll
                for (int nt = 0; nt < 8; nt++) {
                    int c = wn * 64 + nt * 8 + tig * 2;
                    float2 bb = __ldg((const float2*)(pb1 + c));
                    float v0 = fmaxf(acc[mt][nt][0] + bb.x, 0.f);
                    float v1 = fmaxf(acc[mt][nt][1] + bb.y, 0.f);
                    float v2 = fmaxf(acc[mt][nt][2] + bb.x, 0.f);
                    float v3 = fmaxf(acc[mt][nt][3] + bb.y, 0.f);
                    unsigned short h0, l0, h1, l1, h2, l2, h3, l3;
                    split1(v0, h0, l0); split1(v1, h1, l1);
                    split1(v2, h2, l2); split1(v3, h3, l3);
                    Ahi[r * SAP + c] = h0;       Ahi[r * SAP + c + 1] = h1;
                    Alo[r * SAP + c] = l0;       Alo[r * SAP + c + 1] = l1;
                    Ahi[(r + 8) * SAP + c] = h2; Ahi[(r + 8) * SAP + c + 1] = h3;
                    Alo[(r + 8) * SAP + c] = l2; Alo[(r + 8) * SAP + c + 1] = l3;
                }
            }
        }
    }

    {
        float s0 = 0.f, s1 = 0.f, s2 = 0.f, s3 = 0.f;
        #pragma unroll
        for (int nt = 0; nt < 8; nt++) {
            int c = wn * 64 + nt * 8 + tig * 2;
            float2 bb = __ldg((const float2*)(pb2 + c));
            float w0 = __ldg(pw3 + c);
            float w1 = __ldg(pw3 + c + 1);
            s0 += fmaxf(acc[0][nt][0] + bb.x, 0.f) * w0 + fmaxf(acc[0][nt][1] + bb.y, 0.f) * w1;
            s1 += fmaxf(acc[0][nt][2] + bb.x, 0.f) * w0 + fmaxf(acc[0][nt][3] + bb.y, 0.f) * w1;
            s2 += fmaxf(acc[1][nt][0] + bb.x, 0.f) * w0 + fmaxf(acc[1][nt][1] + bb.y, 0.f) * w1;
            s3 += fmaxf(acc[1][nt][2] + bb.x, 0.f) * w0 + fmaxf(acc[1][nt][3] + bb.y, 0.f) * w1;
        }
        #pragma unroll
        for (int dd = 1; dd < 4; dd <<= 1) {
            s0 += __shfl_xor_sync(0xffffffffu, s0, dd);
            s1 += __shfl_xor_sync(0xffffffffu, s1, dd);
            s2 += __shfl_xor_sync(0xffffffffu, s2, dd);
            s3 += __shfl_xor_sync(0xffffffffu, s3, dd);
        }
        if (tig == 0) {
            int r = wm * 32 + g8;
            red[r][wn]      = s0;
            red[r + 8][wn]  = s1;
            red[r + 16][wn] = s2;
            red[r + 24][wn] = s3;
        }
    }
    __syncthreads();
    if (t < 128 && p0 + t < PP)
        outp[p0 + t] = red[t][0] + red[t][1] + __ldg(pb3);
}

// ---------------------------------------------------------------------------
extern "C" void kernel_launch(void* const* d_in, const int* in_sizes, int n_in,
                              void* d_out, int out_size)
{
    const float* x     = (const float*)d_in[0];
    const int* src[3]  = {(const int*)d_in[1], (const int*)d_in[4], (const int*)d_in[7]};
    const int* dst[3]  = {(const int*)d_in[2], (const int*)d_in[5], (const int*)d_in[8]};
    const float* w[3]  = {(const float*)d_in[3], (const float*)d_in[6], (const float*)d_in[9]};
    const int* pos_src = (const int*)d_in[10];
    const int* pos_dst = (const int*)d_in[11];
    const int* neg_src = (const int*)d_in[12];
    const int* neg_dst = (const int*)d_in[13];
    const float* Wself[3]  = {(const float*)d_in[14], (const float*)d_in[17], (const float*)d_in[20]};
    const float* Wneigh[3] = {(const float*)d_in[15], (const float*)d_in[18], (const float*)d_in[21]};
    const float* bvec[3]   = {(const float*)d_in[16], (const float*)d_in[19], (const float*)d_in[22]};
    const float* pw1 = (const float*)d_in[23];
    const float* pb1 = (const float*)d_in[24];
    const float* pw2 = (const float*)d_in[25];
    const float* pb2 = (const float*)d_in[26];
    const float* pw3 = (const float*)d_in[27];
    const float* pb3 = (const float*)d_in[28];

    float* out = (float*)d_out;
    float* h_final = out + 2 * PP;

    void *hA_p, *hB_p, *bth_p, *btl_p;
    cudaGetSymbolAddress(&hA_p, g_hA);
    cudaGetSymbolAddress(&hB_p, g_hB);
    cudaGetSymbolAddress(&bth_p, g_bt_hi);
    cudaGetSymbolAddress(&btl_p, g_bt_lo);
    float* hA = (float*)hA_p;
    float* hB = (float*)hB_p;
    unsigned short* bth = (unsigned short*)bth_p;
    unsigned short* btl = (unsigned short*)btl_p;

    static bool attr_set = false;
    if (!attr_set) {
        cudaFuncSetAttribute(sage_node_mma, cudaFuncAttributeMaxDynamicSharedMemorySize, SMEM_NODE);
        cudaFuncSetAttribute(pred_mma, cudaFuncAttributeMaxDynamicSharedMemorySize, SMEM_PRED);
        attr_set = true;
    }

    const int node_blocks = (NN + 127) / 128;
    const int agg_blocks  = (NN + 7) / 8;

    const float* layer_in[3]  = {x, hA, hB};
    float*       layer_out[3] = {hA, hB, h_final};

    convp_kernel<<<128, 256>>>(pw1, pw2);
    for (int l = 0; l < 3; l++)
        convw_kernel<<<128, 256>>>(Wself[l], Wneigh[l],
                                   bth + l * 32768, btl + l * 32768);

    for (int l = 0; l < 3; l++) {
        hist_kernel<<<EDGE_BLKS, 256>>>(dst[l]);
        scan1_kernel<<<SCAN_BLKS, 256>>>();
        scan2_kernel<<<1, 512>>>();
        scan3_kernel<<<SCAN_BLKS, 256>>>();
        scatter_kernel<<<EDGE_BLKS, 256>>>(src[l], dst[l], w[l]);
        aggregate_kernel<<<agg_blocks, 256>>>(layer_in[l]);
        sage_node_mma<<<node_blocks, 256, SMEM_NODE>>>(
            layer_in[l], bth + l * 32768, btl + l * 32768,
            bvec[l], layer_out[l], l < 2 ? 1 : 0);
    }

    pred_mma<<<2 * PB, 256, SMEM_PRED>>>(h_final, pos_src, pos_dst, neg_src, neg_dst,
                                         pb1, pb2, pw3, pb3, out);
}